// round 13
// baseline (speedup 1.0000x reference)
#include <cuda_runtime.h>
#include <cstdint>

// GRU teacher-forced NLL, B=8192, S=2048, H=8, IN_DIM=4, MAX_COUNT=10.
// R11: 4 lanes per batch element (group via shfl.xor 1/2) -> 32768 threads,
//      1024 warps, 2 warps/SMSP on 128 SMs => MUFU/FMA/latency overlap.
//   lane q (=tid&3) owns hidden units {2q,2q+1} and classes {q, q+4, 8+q(*)}
//   (*) classes 10/11 for q>=2 are dummies: zero weights, bias -100 (ex2->0).
// Weights register-resident (columns permuted per-lane into shfl slot order),
// input contribution via 10-entry shared tables (pre-scaled).
// Accurate activations via ex2/rcp (bit-identical to R8 path, rel_err ~1e-7):
//   sigmoid(x) = rcp(1 + ex2(-x*log2e))
//   tanh(x)    = 1 - 2*rcp(1 + ex2(2x*log2e))
// Softmax in log2 domain, no max shift (logits provably bounded).

#define NBLK 128
#define NTHR 256
#define SSTEPS 2048

typedef unsigned long long u64;

__device__ float g_partials[NBLK];

__device__ __forceinline__ float fast_ex2(float x) {
    float y; asm("ex2.approx.f32 %0, %1;" : "=f"(y) : "f"(x)); return y;
}
__device__ __forceinline__ float fast_lg2(float x) {
    float y; asm("lg2.approx.f32 %0, %1;" : "=f"(y) : "f"(x)); return y;
}
__device__ __forceinline__ float fast_rcp(float x) {
    float y; asm("rcp.approx.f32 %0, %1;" : "=f"(y) : "f"(x)); return y;
}
__device__ __forceinline__ u64 pack2(float lo, float hi) {
    u64 r; asm("mov.b64 %0, {%1, %2};" : "=l"(r) : "f"(lo), "f"(hi)); return r;
}
__device__ __forceinline__ u64 dup2(float v) {
    u64 r; asm("mov.b64 %0, {%1, %1};" : "=l"(r) : "f"(v)); return r;
}
__device__ __forceinline__ void unpack2(float& lo, float& hi, u64 v) {
    asm("mov.b64 {%0, %1}, %2;" : "=f"(lo), "=f"(hi) : "l"(v));
}
__device__ __forceinline__ u64 fma2(u64 a, u64 b, u64 c) {
    u64 d; asm("fma.rn.f32x2 %0, %1, %2, %3;" : "=l"(d) : "l"(a), "l"(b), "l"(c));
    return d;
}

__global__ __launch_bounds__(NTHR) void gru_kernel(
    const int* __restrict__ x,
    const float* __restrict__ Wir, const float* __restrict__ bir,
    const float* __restrict__ Wiz, const float* __restrict__ biz,
    const float* __restrict__ Win, const float* __restrict__ bin_,
    const float* __restrict__ Whr, const float* __restrict__ bhr,
    const float* __restrict__ Whz, const float* __restrict__ bhz,
    const float* __restrict__ Whn, const float* __restrict__ bhn,
    const float* __restrict__ Wout, const float* __restrict__ bout)
{
    __shared__ __align__(16) float tbl[240];   // [gate(3)][count(10)][unit(8)]
    __shared__ float wsum[NTHR / 32];

    const int tid = threadIdx.x;
    const int q   = tid & 3;                       // lane within element group
    const int e   = blockIdx.x * (NTHR / 4) + (tid >> 2);
    const float LOG2E  = 1.4426950408889634f;
    const float NL2E   = -1.4426950408889634f;     // -log2e (sigmoid path)
    const float TL2E   =  2.8853900817779268f;     // 2*log2e (tanh path)

    // ---- build input tables: ALL 240 entries ----
    for (int idx = tid; idx < 240; idx += NTHR) {
        int g = idx / 80, rem = idx % 80, c = rem / 8, i = rem % 8;
        const float* Wi = (g == 0) ? Wir : (g == 1) ? Wiz : Win;
        const float* bi = (g == 0) ? bir : (g == 1) ? biz : bin_;
        float v = bi[i];
        if (g == 0) v += bhr[i];
        if (g == 1) v += bhz[i];
        #pragma unroll
        for (int k = 0; k < 4; k++)
            if (c & (1 << (3 - k))) v += Wi[i * 4 + k];   // MSB-first bits
        v *= (g < 2) ? NL2E : TL2E;
        tbl[idx] = v;
    }

    // ---- per-lane packed weights, columns in shfl slot order ----
    // slot s holds the h-pair of lane q^s => column m covers unit 2*(q^(m>>1)) + (m&1)
    const int r0 = 2 * q, r1 = r0 + 1;
    u64 wr2[8], wz2[8], wn2[8], woP[8];
    float woE[8];
    const bool hasE = (q < 2);
    const int cA = q, cB = q + 4, cE = 8 + q;      // cE=10/11 for q>=2: never matches tgt
    #pragma unroll
    for (int m = 0; m < 8; m++) {
        int col = 2 * (q ^ (m >> 1)) + (m & 1);
        wr2[m] = pack2(NL2E * Whr[r0 * 8 + col], NL2E * Whr[r1 * 8 + col]);
        wz2[m] = pack2(NL2E * Whz[r0 * 8 + col], NL2E * Whz[r1 * 8 + col]);
        wn2[m] = pack2(TL2E * Whn[r0 * 8 + col], TL2E * Whn[r1 * 8 + col]);
        woP[m] = pack2(LOG2E * Wout[cA * 8 + col], LOG2E * Wout[cB * 8 + col]);
        woE[m] = hasE ? LOG2E * Wout[cE * 8 + col] : 0.f;
    }
    const u64 bhn2 = pack2(TL2E * bhn[r0], TL2E * bhn[r1]);
    const u64 boP  = pack2(LOG2E * bout[cA], LOG2E * bout[cB]);
    const float boE = hasE ? LOG2E * bout[cE] : -100.f;   // ex2(-100) ~ 0
    __syncthreads();

    const u64* t8 = (const u64*)tbl;   // pair granules: (g*10+c)*4 + p

    float hs[8];                        // all 8 h values, slot order
    #pragma unroll
    for (int m = 0; m < 8; m++) hs[m] = 0.f;
    float loss2 = 0.f;

    const int4* row4 = (const int4*)(x + (size_t)e * SSTEPS);
    int4 cur = row4[0];
    int prev_c = 0;

    #pragma unroll 1
    for (int blk = 0; blk < SSTEPS / 4; blk++) {
        int4 nxt = cur;
        if (blk < SSTEPS / 4 - 1) nxt = row4[blk + 1];
        int tg0 = cur.x, tg1 = cur.y, tg2 = cur.z, tg3 = cur.w;
        #pragma unroll
        for (int s = 0; s < 4; s++) {
            const int c   = prev_c;
            const int tgt = (s == 0) ? tg0 : (s == 1) ? tg1 : (s == 2) ? tg2 : tg3;
            prev_c = tgt;

            // input tables for my unit pair (pre-scaled)
            const int ti = c * 4 + q;
            u64 ar2 = t8[ti];
            u64 az2 = t8[40 + ti];
            u64 tn2 = t8[80 + ti];
            u64 an2 = bhn2;

            // hidden matvec: packed FFMA2 over all 8 h (slot order)
            #pragma unroll
            for (int m = 0; m < 8; m++) {
                u64 hm = dup2(hs[m]);
                ar2 = fma2(wr2[m], hm, ar2);
                az2 = fma2(wz2[m], hm, az2);
                an2 = fma2(wn2[m], hm, an2);
            }

            float ar0, ar1, az0, az1, an0, an1, tn0, tn1;
            unpack2(ar0, ar1, ar2);
            unpack2(az0, az1, az2);
            unpack2(an0, an1, an2);
            unpack2(tn0, tn1, tn2);

            // accurate activations + state update for my 2 units
            float h0 = hs[0], h1 = hs[1];
            float rr0 = fast_rcp(1.f + fast_ex2(ar0));
            float zz0 = fast_rcp(1.f + fast_ex2(az0));
            float ss0 = fmaf(rr0, an0, tn0);
            float nn0 = fmaf(-2.f, fast_rcp(1.f + fast_ex2(ss0)), 1.f);
            float h0n = fmaf(zz0, h0 - nn0, nn0);
            float rr1 = fast_rcp(1.f + fast_ex2(ar1));
            float zz1 = fast_rcp(1.f + fast_ex2(az1));
            float ss1 = fmaf(rr1, an1, tn1);
            float nn1 = fmaf(-2.f, fast_rcp(1.f + fast_ex2(ss1)), 1.f);
            float h1n = fmaf(zz1, h1 - nn1, nn1);

            // distribute h pairs across the 4-lane group (3 x 64-bit shfl)
            u64 hp0 = pack2(h0n, h1n);
            u64 hp1 = __shfl_xor_sync(0xffffffffu, hp0, 1);
            u64 hp2 = __shfl_xor_sync(0xffffffffu, hp0, 2);
            u64 hp3 = __shfl_xor_sync(0xffffffffu, hp1, 2);  // lane q^3's pair
            unpack2(hs[0], hs[1], hp0);
            unpack2(hs[2], hs[3], hp1);
            unpack2(hs[4], hs[5], hp2);
            unpack2(hs[6], hs[7], hp3);

            // logits (log2-scaled): packed pair (cA,cB) + scalar extra class
            u64 lP = boP;
            float lE = boE;
            #pragma unroll
            for (int m = 0; m < 8; m++) {
                u64 hm = dup2(hs[m]);
                lP = fma2(woP[m], hm, lP);
                lE = fmaf(woE[m], hs[m], lE);
            }
            float l0, l1;
            unpack2(l0, l1, lP);

            // log-softmax NLL across the 4-lane group, log2 domain, no max shift
            float esum = fast_ex2(l0) + fast_ex2(l1) + fast_ex2(lE);
            esum += __shfl_xor_sync(0xffffffffu, esum, 1);
            esum += __shfl_xor_sync(0xffffffffu, esum, 2);
            float lse2 = fast_lg2(esum);

            float contrib = (tgt == cA) ? l0 : (tgt == cB) ? l1 : (tgt == cE) ? lE : 0.f;
            contrib += __shfl_xor_sync(0xffffffffu, contrib, 1);
            contrib += __shfl_xor_sync(0xffffffffu, contrib, 2);

            loss2 += lse2 - contrib;   // nll * log2e (all 4 lanes identical)
        }
        cur = nxt;
    }

    // ---- deterministic block reduction ----
    #pragma unroll
    for (int off = 16; off; off >>= 1)
        loss2 += __shfl_xor_sync(0xffffffffu, loss2, off);
    if ((tid & 31) == 0) wsum[tid >> 5] = loss2;
    __syncthreads();
    if (tid == 0) {
        float t = 0.f;
        #pragma unroll
        for (int w = 0; w < NTHR / 32; w++) t += wsum[w];
        g_partials[blockIdx.x] = t;
    }
}

__global__ void finalize_kernel(float* __restrict__ out)
{
    __shared__ float s[4];
    int tid = threadIdx.x;
    float v = g_partials[tid];
    #pragma unroll
    for (int off = 16; off; off >>= 1)
        v += __shfl_xor_sync(0xffffffffu, v, off);
    if ((tid & 31) == 0) s[tid >> 5] = v;
    __syncthreads();
    if (tid == 0) {
        // each element counted 4x (four lanes), log2 units -> nats, mean over B*S
        const float scale = (float)(0.6931471805599453 / (4.0 * 8192.0 * 2048.0));
        out[0] = (s[0] + s[1] + s[2] + s[3]) * scale;
    }
}

extern "C" void kernel_launch(void* const* d_in, const int* in_sizes, int n_in,
                              void* d_out, int out_size)
{
    (void)in_sizes; (void)n_in; (void)out_size;
    const int*   x    = (const int*)  d_in[0];
    const float* Wir  = (const float*)d_in[1];
    const float* bir  = (const float*)d_in[2];
    const float* Wiz  = (const float*)d_in[3];
    const float* biz  = (const float*)d_in[4];
    const float* Win  = (const float*)d_in[5];
    const float* bin_ = (const float*)d_in[6];
    const float* Whr  = (const float*)d_in[7];
    const float* bhr  = (const float*)d_in[8];
    const float* Whz  = (const float*)d_in[9];
    const float* bhz  = (const float*)d_in[10];
    const float* Whn  = (const float*)d_in[11];
    const float* bhn  = (const float*)d_in[12];
    const float* Wout = (const float*)d_in[13];
    const float* bout = (const float*)d_in[14];

    gru_kernel<<<NBLK, NTHR>>>(x, Wir, bir, Wiz, biz, Win, bin_,
                               Whr, bhr, Whz, bhz, Whn, bhn, Wout, bout);
    finalize_kernel<<<1, NBLK>>>((float*)d_out);
}

// round 14
// speedup vs baseline: 1.4544x; 1.4544x over previous
#include <cuda_runtime.h>
#include <cstdint>

// GRU teacher-forced NLL, B=8192, S=2048, H=8, IN_DIM=4, MAX_COUNT=10.
// Base: R8 structure (2 lanes/element, packed FFMA2, 487us, rel_err 1e-7).
// R13 lesson: 4-lane split adds redundant work -> regression; reverted.
// This round: all three activations via tanh.approx.f32 (1 MUFU each):
//   sigmoid(x) = 0.5*tanh(x/2) + 0.5   (0.5 pre-folded into gate weights/tables)
//   tanh(x)    = tanh.approx(x)        (n-path unscaled)
// MUFU per warp-step: 30 -> 18. Softmax still exact-ish ex2/lg2 in log2 domain.

#define NBLK 128
#define NTHR 128
#define SSTEPS 2048

typedef unsigned long long u64;

__device__ float g_partials[NBLK];

__device__ __forceinline__ float fast_ex2(float x) {
    float y; asm("ex2.approx.f32 %0, %1;" : "=f"(y) : "f"(x)); return y;
}
__device__ __forceinline__ float fast_lg2(float x) {
    float y; asm("lg2.approx.f32 %0, %1;" : "=f"(y) : "f"(x)); return y;
}
__device__ __forceinline__ float fast_tanh(float x) {
    float y; asm("tanh.approx.f32 %0, %1;" : "=f"(y) : "f"(x)); return y;
}
__device__ __forceinline__ u64 pack2(float lo, float hi) {
    u64 r; asm("mov.b64 %0, {%1, %2};" : "=l"(r) : "f"(lo), "f"(hi)); return r;
}
__device__ __forceinline__ u64 dup2(float v) {
    u64 r; asm("mov.b64 %0, {%1, %1};" : "=l"(r) : "f"(v)); return r;
}
__device__ __forceinline__ void unpack2(float& lo, float& hi, u64 v) {
    asm("mov.b64 {%0, %1}, %2;" : "=f"(lo), "=f"(hi) : "l"(v));
}
__device__ __forceinline__ u64 fma2(u64 a, u64 b, u64 c) {
    u64 d; asm("fma.rn.f32x2 %0, %1, %2, %3;" : "=l"(d) : "l"(a), "l"(b), "l"(c));
    return d;
}

__global__ __launch_bounds__(NTHR) void gru_kernel(
    const int* __restrict__ x,
    const float* __restrict__ Wir, const float* __restrict__ bir,
    const float* __restrict__ Wiz, const float* __restrict__ biz,
    const float* __restrict__ Win, const float* __restrict__ bin_,
    const float* __restrict__ Whr, const float* __restrict__ bhr,
    const float* __restrict__ Whz, const float* __restrict__ bhz,
    const float* __restrict__ Whn, const float* __restrict__ bhn,
    const float* __restrict__ Wout, const float* __restrict__ bout)
{
    __shared__ __align__(16) float tbl[240];   // [gate(3)][count(10)][unit(8)]
    __shared__ float wsum[4];

    const int tid  = threadIdx.x;
    const int half = tid & 1;
    const int e    = blockIdx.x * (NTHR / 2) + (tid >> 1);
    const float LOG2E = 1.4426950408889634f;

    // ---- build input tables: ALL 240 entries ----
    // r/z tables hold pre/2 (sigmoid-as-tanh); n table holds pre unscaled.
    for (int idx = tid; idx < 240; idx += NTHR) {
        int g = idx / 80, rem = idx % 80, c = rem / 8, i = rem % 8;
        const float* Wi = (g == 0) ? Wir : (g == 1) ? Wiz : Win;
        const float* bi = (g == 0) ? bir : (g == 1) ? biz : bin_;
        float v = bi[i];
        if (g == 0) v += bhr[i];
        if (g == 1) v += bhz[i];
        #pragma unroll
        for (int k = 0; k < 4; k++)
            if (c & (1 << (3 - k))) v += Wi[i * 4 + k];   // MSB-first bits
        if (g < 2) v *= 0.5f;
        tbl[idx] = v;
    }

    // ---- packed per-thread weights (columns permuted: my units first) ----
    u64 wr2[2][8], wz2[2][8], wn2[2][8], bhn2[2];
    #pragma unroll
    for (int p = 0; p < 2; p++) {
        int r0 = half * 4 + 2 * p, r1 = r0 + 1;
        bhn2[p] = pack2(bhn[r0], bhn[r1]);
        #pragma unroll
        for (int jj = 0; jj < 8; jj++) {
            int col = (jj + half * 4) & 7;
            wr2[p][jj] = pack2(0.5f * Whr[r0 * 8 + col], 0.5f * Whr[r1 * 8 + col]);
            wz2[p][jj] = pack2(0.5f * Whz[r0 * 8 + col], 0.5f * Whz[r1 * 8 + col]);
            wn2[p][jj] = pack2(Whn[r0 * 8 + col], Whn[r1 * 8 + col]);
        }
    }
    // Logit weights: classes half*5 + {0..4}; (0,1),(2,3) packed, 4 scalar.
    u64 wo01[8], wo23[8];
    float wo4[8];
    {
        int c0 = half * 5;
        #pragma unroll
        for (int jj = 0; jj < 8; jj++) {
            int col = (jj + half * 4) & 7;
            wo01[jj] = pack2(LOG2E * Wout[(c0 + 0) * 8 + col], LOG2E * Wout[(c0 + 1) * 8 + col]);
            wo23[jj] = pack2(LOG2E * Wout[(c0 + 2) * 8 + col], LOG2E * Wout[(c0 + 3) * 8 + col]);
            wo4[jj]  = LOG2E * Wout[(c0 + 4) * 8 + col];
        }
    }
    u64 bo01, bo23; float bo4;
    {
        int c0 = half * 5;
        bo01 = pack2(LOG2E * bout[c0 + 0], LOG2E * bout[c0 + 1]);
        bo23 = pack2(LOG2E * bout[c0 + 2], LOG2E * bout[c0 + 3]);
        bo4  = LOG2E * bout[c0 + 4];
    }
    __syncthreads();

    const ulonglong2* t2 = (const ulonglong2*)tbl;   // 16B granules, pair layout

    float myh[4] = {0.f, 0.f, 0.f, 0.f};
    float oh[4]  = {0.f, 0.f, 0.f, 0.f};
    float loss2  = 0.f;

    const int4* row4 = (const int4*)(x + (size_t)e * SSTEPS);
    int4 cur = row4[0];
    int prev_c = 0;

    #pragma unroll 1
    for (int blk = 0; blk < SSTEPS / 4; blk++) {
        int4 nxt = cur;
        if (blk < SSTEPS / 4 - 1) nxt = row4[blk + 1];
        int tg0 = cur.x, tg1 = cur.y, tg2 = cur.z, tg3 = cur.w;
        #pragma unroll
        for (int s = 0; s < 4; s++) {
            const int c   = prev_c;
            const int tgt = (s == 0) ? tg0 : (s == 1) ? tg1 : (s == 2) ? tg2 : tg3;
            prev_c = tgt;

            // input tables for my 4 units (packed-pair form)
            const int ti = c * 2 + half;
            ulonglong2 trv = t2[ti];
            ulonglong2 tzv = t2[20 + ti];
            ulonglong2 tnv = t2[40 + ti];

            u64 ar2[2] = {trv.x, trv.y};
            u64 az2[2] = {tzv.x, tzv.y};
            u64 an2[2] = {bhn2[0], bhn2[1]};

            // hidden matvec: packed FFMA2, my half then partner half
            #pragma unroll
            for (int j = 0; j < 4; j++) {
                u64 h2 = dup2(myh[j]);
                ar2[0] = fma2(wr2[0][j], h2, ar2[0]);
                ar2[1] = fma2(wr2[1][j], h2, ar2[1]);
                az2[0] = fma2(wz2[0][j], h2, az2[0]);
                az2[1] = fma2(wz2[1][j], h2, az2[1]);
                an2[0] = fma2(wn2[0][j], h2, an2[0]);
                an2[1] = fma2(wn2[1][j], h2, an2[1]);
            }
            #pragma unroll
            for (int j = 0; j < 4; j++) {
                u64 h2 = dup2(oh[j]);
                ar2[0] = fma2(wr2[0][4 + j], h2, ar2[0]);
                ar2[1] = fma2(wr2[1][4 + j], h2, ar2[1]);
                az2[0] = fma2(wz2[0][4 + j], h2, az2[0]);
                az2[1] = fma2(wz2[1][4 + j], h2, az2[1]);
                an2[0] = fma2(wn2[0][4 + j], h2, an2[0]);
                an2[1] = fma2(wn2[1][4 + j], h2, an2[1]);
            }

            float ar[4], az[4], an[4], tn[4];
            unpack2(ar[0], ar[1], ar2[0]); unpack2(ar[2], ar[3], ar2[1]);
            unpack2(az[0], az[1], az2[0]); unpack2(az[2], az[3], az2[1]);
            unpack2(an[0], an[1], an2[0]); unpack2(an[2], an[3], an2[1]);
            unpack2(tn[0], tn[1], tnv.x);  unpack2(tn[2], tn[3], tnv.y);

            // activations via tanh.approx (3 MUFU/unit)
            // r = 0.5*trh+0.5; r*an = 0.5*(trh*an + an)
            // npre = tn + 0.5*fma(trh, an, an); n = tanh(npre)
            // z = 0.5*tzh+0.5; h' = n + z*(h-n)
            float h_new[4];
            #pragma unroll
            for (int u = 0; u < 4; u++) {
                float trh  = fast_tanh(ar[u]);
                float tzh  = fast_tanh(az[u]);
                float npre = fmaf(0.5f, fmaf(trh, an[u], an[u]), tn[u]);
                float n    = fast_tanh(npre);
                float z    = fmaf(0.5f, tzh, 0.5f);
                h_new[u]   = fmaf(z, myh[u] - n, n);
            }
            #pragma unroll
            for (int u = 0; u < 4; u++) {
                myh[u] = h_new[u];
                oh[u]  = __shfl_xor_sync(0xffffffffu, h_new[u], 1);
            }

            // logits (log2-scaled): packed class pairs (0,1),(2,3) + scalar 4
            u64 l01 = bo01, l23 = bo23;
            float l4 = bo4;
            #pragma unroll
            for (int j = 0; j < 4; j++) {
                u64 h2 = dup2(myh[j]);
                l01 = fma2(wo01[j], h2, l01);
                l23 = fma2(wo23[j], h2, l23);
                l4  = fmaf(wo4[j], myh[j], l4);
            }
            #pragma unroll
            for (int j = 0; j < 4; j++) {
                u64 h2 = dup2(oh[j]);
                l01 = fma2(wo01[4 + j], h2, l01);
                l23 = fma2(wo23[4 + j], h2, l23);
                l4  = fmaf(wo4[4 + j], oh[j], l4);
            }
            float l[5];
            unpack2(l[0], l[1], l01);
            unpack2(l[2], l[3], l23);
            l[4] = l4;

            // log-softmax NLL across the lane pair, log2 domain, no max shift
            float esum = fast_ex2(l[0]);
            esum += fast_ex2(l[1]);
            esum += fast_ex2(l[2]);
            esum += fast_ex2(l[3]);
            esum += fast_ex2(l[4]);
            esum += __shfl_xor_sync(0xffffffffu, esum, 1);
            float lse2 = fast_lg2(esum);

            // target logit: zero-masked contribution, summed across the pair
            int k = tgt - half * 5;
            float contrib = 0.f;
            contrib = (k == 0) ? l[0] : contrib;
            contrib = (k == 1) ? l[1] : contrib;
            contrib = (k == 2) ? l[2] : contrib;
            contrib = (k == 3) ? l[3] : contrib;
            contrib = (k == 4) ? l[4] : contrib;
            float lt = contrib + __shfl_xor_sync(0xffffffffu, contrib, 1);

            loss2 += lse2 - lt;   // nll * log2e (both lanes identical)
        }
        cur = nxt;
    }

    // ---- deterministic block reduction ----
    #pragma unroll
    for (int off = 16; off; off >>= 1)
        loss2 += __shfl_xor_sync(0xffffffffu, loss2, off);
    if ((tid & 31) == 0) wsum[tid >> 5] = loss2;
    __syncthreads();
    if (tid == 0)
        g_partials[blockIdx.x] = wsum[0] + wsum[1] + wsum[2] + wsum[3];
}

__global__ void finalize_kernel(float* __restrict__ out)
{
    __shared__ float s[4];
    int tid = threadIdx.x;
    float v = g_partials[tid];
    #pragma unroll
    for (int off = 16; off; off >>= 1)
        v += __shfl_xor_sync(0xffffffffu, v, off);
    if ((tid & 31) == 0) s[tid >> 5] = v;
    __syncthreads();
    if (tid == 0) {
        // each element counted twice (both lanes), log2 units -> nats, mean over B*S
        const float scale = (float)(0.6931471805599453 / (2.0 * 8192.0 * 2048.0));
        out[0] = (s[0] + s[1] + s[2] + s[3]) * scale;
    }
}

extern "C" void kernel_launch(void* const* d_in, const int* in_sizes, int n_in,
                              void* d_out, int out_size)
{
    (void)in_sizes; (void)n_in; (void)out_size;
    const int*   x    = (const int*)  d_in[0];
    const float* Wir  = (const float*)d_in[1];
    const float* bir  = (const float*)d_in[2];
    const float* Wiz  = (const float*)d_in[3];
    const float* biz  = (const float*)d_in[4];
    const float* Win  = (const float*)d_in[5];
    const float* bin_ = (const float*)d_in[6];
    const float* Whr  = (const float*)d_in[7];
    const float* bhr  = (const float*)d_in[8];
    const float* Whz  = (const float*)d_in[9];
    const float* bhz  = (const float*)d_in[10];
    const float* Whn  = (const float*)d_in[11];
    const float* bhn  = (const float*)d_in[12];
    const float* Wout = (const float*)d_in[13];
    const float* bout = (const float*)d_in[14];

    gru_kernel<<<NBLK, NTHR>>>(x, Wir, bir, Wiz, biz, Win, bin_,
                               Whr, bhr, Whz, bhz, Whn, bhn, Wout, bout);
    finalize_kernel<<<1, NBLK>>>((float*)d_out);
}